// round 3
// baseline (speedup 1.0000x reference)
#include <cuda_runtime.h>
#include <cuda_bf16.h>
#include <stdint.h>

#define N_NODES_C  100000
#define N_GRAPHS_C 128
#define D_NODE 96
#define D_EDGE 32
#define HID 16
#define BN_EPS 1e-5f

#define TILE 512          // edges per block
#define THREADS 256       // 2 edges per thread
#define ASTRIDE 513       // padded stride for transposed attr (conflict-free)
#define PSTRIDE 20        // padded stride for staged p rows (conflict-free loads)
#define NT 256            // node-kernel threads

// shared layout (floats)
#define OFF_ATTR 0
#define OFF_P    (OFF_ATTR + 32 * ASTRIDE)          // 16416
#define OFF_W    (OFF_P + TILE * PSTRIDE)           // +10240
#define OFF_B    (OFF_W + 512)
#define OFF_W2   (OFF_B + 16)
#define OFF_BINS (OFF_W2 + 16)
#define OFF_SRC  (OFF_BINS + 128)
#define SMEM_FLOATS (OFF_SRC + TILE)
#define SMEM_BYTES (SMEM_FLOATS * 4)                // 111,360 B

// -------- scratch (no allocations allowed) --------
__device__ float g_p[N_NODES_C * HID];     // per-node folded first-layer partials (6.4 MB)
__device__ float g_Wx[HID * D_NODE];       // folded W1 (node part), [k][j]
__device__ float g_WeT[D_EDGE * HID];      // folded W1 (edge part), TRANSPOSED [j][k]
__device__ float g_bf[HID];                // folded bias (b1, BN)
__device__ float g_w2[HID];
__device__ float g_b2;

// -------- fold BN into weights; zero output --------
__global__ void prep_kernel(const float* __restrict__ W1, const float* __restrict__ b1,
                            const float* __restrict__ gamma, const float* __restrict__ beta,
                            const float* __restrict__ rm, const float* __restrict__ rv,
                            const float* __restrict__ W2, const float* __restrict__ b2,
                            float* __restrict__ out, int out_n) {
    __shared__ float a[HID];
    int t = threadIdx.x;
    if (t < HID) {
        float ak = gamma[t] * rsqrtf(rv[t] + BN_EPS);
        a[t] = ak;
        g_bf[t] = ak * (b1[t] - rm[t]) + beta[t];
        g_w2[t] = W2[t];
    }
    if (t == 0) g_b2 = b2[0];
    if (t < out_n) out[t] = 0.0f;
    __syncthreads();
    for (int i = t; i < HID * D_NODE; i += blockDim.x) {
        int k = i / D_NODE, j = i % D_NODE;
        g_Wx[i] = a[k] * W1[k * (D_NODE + D_EDGE) + j];
    }
    for (int i = t; i < D_EDGE * HID; i += blockDim.x) {
        int j = i / HID, k = i % HID;               // g_WeT[j*16+k]
        g_WeT[i] = a[k] * W1[k * (D_NODE + D_EDGE) + D_NODE + j];
    }
}

// -------- per-node: p[n][k] = Wx'[k] . x[n] --------
__global__ void __launch_bounds__(NT) node_kernel(const float* __restrict__ x, int n_nodes) {
    __shared__ float sW[HID * D_NODE];      // 6 KB
    for (int i = threadIdx.x; i < HID * D_NODE; i += blockDim.x) sW[i] = g_Wx[i];
    __syncthreads();
    int n = blockIdx.x * blockDim.x + threadIdx.x;
    if (n >= n_nodes) return;
    float acc[HID];
#pragma unroll
    for (int k = 0; k < HID; k++) acc[k] = 0.0f;
    const float4* xr = (const float4*)(x + (size_t)n * D_NODE);
#pragma unroll
    for (int jj = 0; jj < D_NODE / 4; jj++) {
        float4 v = __ldg(xr + jj);
#pragma unroll
        for (int k = 0; k < HID; k++) {
            const float4 w = *(const float4*)(sW + k * D_NODE + jj * 4);
            acc[k] += w.x * v.x + w.y * v.y + w.z * v.z + w.w * v.w;
        }
    }
    float4* po = (float4*)(g_p + (size_t)n * HID);
    po[0] = make_float4(acc[0], acc[1], acc[2], acc[3]);
    po[1] = make_float4(acc[4], acc[5], acc[6], acc[7]);
    po[2] = make_float4(acc[8], acc[9], acc[10], acc[11]);
    po[3] = make_float4(acc[12], acc[13], acc[14], acc[15]);
}

// -------- per-edge: msg + pooled accumulation (2 edges per thread) --------
__global__ void __launch_bounds__(THREADS, 2) edge_kernel(
    const float* __restrict__ edge_attr,
    const int* __restrict__ ei,             // [2][E] int32
    const int* __restrict__ batch,          // [N]    int32
    float* __restrict__ out,                // [G]
    int n_edges) {
    extern __shared__ float sm[];
    float* sAttrT = sm + OFF_ATTR;
    float* sP     = sm + OFF_P;
    float* sW     = sm + OFF_W;
    float* sB     = sm + OFF_B;
    float* sW2v   = sm + OFF_W2;
    float* bins   = sm + OFF_BINS;
    int*   sSrc   = (int*)(sm + OFF_SRC);

    const int t  = threadIdx.x;
    const int e0 = blockIdx.x * TILE;
    const int eA = e0 + t;
    const int eB = e0 + t + 256;
    const bool vA = eA < n_edges;
    const bool vB = eB < n_edges;

    // weights / bins / src staging
    for (int i = t; i < D_EDGE * HID; i += THREADS) sW[i] = g_WeT[i];
    if (t < HID) { sB[t] = g_bf[t]; sW2v[t] = g_w2[t]; }
    if (t < N_GRAPHS_C) bins[t] = 0.0f;

    int srcA = 0, srcB = 0, gA = 0, gB = 0;
    if (vA) { srcA = __ldg(ei + eA); gA = __ldg(batch + __ldg(ei + n_edges + eA)); }
    if (vB) { srcB = __ldg(ei + eB); gB = __ldg(batch + __ldg(ei + n_edges + eB)); }
    sSrc[t] = srcA;
    sSrc[t + 256] = srcB;
    __syncthreads();

    // stage edge_attr transposed (coalesced LDG.128, conflict-free STS.32)
    {
        const float4* ga = (const float4*)edge_attr;
        const long long base  = (long long)e0 * (D_EDGE / 4);
        const long long total = (long long)n_edges * (D_EDGE / 4);
#pragma unroll
        for (int r = 0; r < (TILE * (D_EDGE / 4)) / THREADS; r++) {   // 16 rounds
            int idx = r * THREADS + t;
            float4 v = make_float4(0.f, 0.f, 0.f, 0.f);
            if (base + idx < total) v = __ldg(ga + base + idx);
            int el = idx >> 3;
            int j4 = (idx & 7) * 4;
            sAttrT[(j4 + 0) * ASTRIDE + el] = v.x;
            sAttrT[(j4 + 1) * ASTRIDE + el] = v.y;
            sAttrT[(j4 + 2) * ASTRIDE + el] = v.z;
            sAttrT[(j4 + 3) * ASTRIDE + el] = v.w;
        }
        // cooperative p gather: 4 lanes per edge, lanes of one edge hit one 128B line
#pragma unroll
        for (int r = 0; r < (TILE * 4) / THREADS; r++) {              // 8 rounds
            int idx = r * THREADS + t;
            int el  = idx >> 2;
            int q   = idx & 3;
            int s   = sSrc[el];
            float4 v = __ldg((const float4*)g_p + (size_t)s * 4 + q);
            *(float4*)(sP + el * PSTRIDE + q * 4) = v;
        }
    }
    __syncthreads();

    // init accumulators = p + folded bias
    float accA[HID], accB[HID];
#pragma unroll
    for (int q = 0; q < 4; q++) {
        float4 pa = *(const float4*)(sP + t * PSTRIDE + q * 4);
        float4 pb = *(const float4*)(sP + (t + 256) * PSTRIDE + q * 4);
        accA[q*4+0] = pa.x + sB[q*4+0]; accA[q*4+1] = pa.y + sB[q*4+1];
        accA[q*4+2] = pa.z + sB[q*4+2]; accA[q*4+3] = pa.w + sB[q*4+3];
        accB[q*4+0] = pb.x + sB[q*4+0]; accB[q*4+1] = pb.y + sB[q*4+1];
        accB[q*4+2] = pb.z + sB[q*4+2]; accB[q*4+3] = pb.w + sB[q*4+3];
    }

#pragma unroll
    for (int j = 0; j < D_EDGE; j++) {
        float a0 = sAttrT[j * ASTRIDE + t];
        float a1 = sAttrT[j * ASTRIDE + t + 256];
        const float4 w0 = *(const float4*)(sW + j * HID + 0);
        const float4 w1 = *(const float4*)(sW + j * HID + 4);
        const float4 w2 = *(const float4*)(sW + j * HID + 8);
        const float4 w3 = *(const float4*)(sW + j * HID + 12);
        accA[0]  += w0.x * a0; accA[1]  += w0.y * a0; accA[2]  += w0.z * a0; accA[3]  += w0.w * a0;
        accA[4]  += w1.x * a0; accA[5]  += w1.y * a0; accA[6]  += w1.z * a0; accA[7]  += w1.w * a0;
        accA[8]  += w2.x * a0; accA[9]  += w2.y * a0; accA[10] += w2.z * a0; accA[11] += w2.w * a0;
        accA[12] += w3.x * a0; accA[13] += w3.y * a0; accA[14] += w3.z * a0; accA[15] += w3.w * a0;
        accB[0]  += w0.x * a1; accB[1]  += w0.y * a1; accB[2]  += w0.z * a1; accB[3]  += w0.w * a1;
        accB[4]  += w1.x * a1; accB[5]  += w1.y * a1; accB[6]  += w1.z * a1; accB[7]  += w1.w * a1;
        accB[8]  += w2.x * a1; accB[9]  += w2.y * a1; accB[10] += w2.z * a1; accB[11] += w2.w * a1;
        accB[12] += w3.x * a1; accB[13] += w3.y * a1; accB[14] += w3.z * a1; accB[15] += w3.w * a1;
    }

    const float b2v = g_b2;
    if (vA) {
        float m = b2v;
#pragma unroll
        for (int k = 0; k < HID; k++) m += sW2v[k] * fmaxf(accA[k], 0.0f);
        atomicAdd(&bins[gA], m);
    }
    if (vB) {
        float m = b2v;
#pragma unroll
        for (int k = 0; k < HID; k++) m += sW2v[k] * fmaxf(accB[k], 0.0f);
        atomicAdd(&bins[gB], m);
    }
    __syncthreads();
    if (t < N_GRAPHS_C) atomicAdd(&out[t], bins[t]);
}

extern "C" void kernel_launch(void* const* d_in, const int* in_sizes, int n_in,
                              void* d_out, int out_size) {
    const float* x         = (const float*)d_in[0];
    const float* edge_attr = (const float*)d_in[1];
    const int*   ei        = (const int*)d_in[2];
    const int*   batch     = (const int*)d_in[3];
    const float* W1        = (const float*)d_in[4];
    const float* b1        = (const float*)d_in[5];
    const float* gamma     = (const float*)d_in[6];
    const float* beta      = (const float*)d_in[7];
    const float* rm        = (const float*)d_in[8];
    const float* rv        = (const float*)d_in[9];
    const float* W2        = (const float*)d_in[10];
    const float* b2        = (const float*)d_in[11];
    float* out = (float*)d_out;

    const int n_nodes = in_sizes[0] / D_NODE;
    const int n_edges = in_sizes[1] / D_EDGE;

    cudaFuncSetAttribute(edge_kernel, cudaFuncAttributeMaxDynamicSharedMemorySize, SMEM_BYTES);

    prep_kernel<<<1, 512>>>(W1, b1, gamma, beta, rm, rv, W2, b2, out, out_size);
    node_kernel<<<(n_nodes + NT - 1) / NT, NT>>>(x, n_nodes);
    edge_kernel<<<(n_edges + TILE - 1) / TILE, THREADS, SMEM_BYTES>>>(edge_attr, ei, batch, out, n_edges);
}

// round 4
// speedup vs baseline: 1.3167x; 1.3167x over previous
#include <cuda_runtime.h>
#include <cuda_bf16.h>
#include <stdint.h>

#define N_NODES_C  100000
#define N_GRAPHS_C 128
#define D_NODE 96
#define D_EDGE 32
#define HID 16
#define BN_EPS 1e-5f

#define TILE 256
#define THREADS 256
#define RSTRIDE 52        // floats per edge row: 32 attr + 16 p + 4 pad (mult of 4; 20t mod 32 distinct per octet)
#define NT 256

// ---- folded parameters: computed on device, copied into __constant__ ----
struct CP {
    float W[D_EDGE][HID];    // folded edge-part of W1, [j][k]
    float B[HID];            // folded bias
    float W2[HID];
    float b2;
    float pad[3];
    float Wx[HID][D_NODE];   // folded node-part of W1, [k][j]
};
__constant__ CP c_par;
__device__   CP g_par;

__device__ float g_p[N_NODES_C * HID];   // per-node first-layer partials (6.4 MB)

// -------- fold BN into weights; zero output --------
__global__ void prep_kernel(const float* __restrict__ W1, const float* __restrict__ b1,
                            const float* __restrict__ gamma, const float* __restrict__ beta,
                            const float* __restrict__ rm, const float* __restrict__ rv,
                            const float* __restrict__ W2, const float* __restrict__ b2,
                            float* __restrict__ out, int out_n) {
    __shared__ float a[HID];
    int lt = threadIdx.x;
    int t  = blockIdx.x * blockDim.x + lt;
    int stride = gridDim.x * blockDim.x;
    if (lt < HID) a[lt] = gamma[lt] * rsqrtf(rv[lt] + BN_EPS);
    __syncthreads();
    for (int i = t; i < D_EDGE * HID; i += stride) {
        int j = i / HID, k = i % HID;
        g_par.W[j][k] = a[k] * W1[k * (D_NODE + D_EDGE) + D_NODE + j];
    }
    for (int i = t; i < HID * D_NODE; i += stride) {
        int k = i / D_NODE, j = i % D_NODE;
        g_par.Wx[k][j] = a[k] * W1[k * (D_NODE + D_EDGE) + j];
    }
    if (t < HID) {
        g_par.B[t]  = a[t] * (b1[t] - rm[t]) + beta[t];
        g_par.W2[t] = W2[t];
    }
    if (t == 0) g_par.b2 = b2[0];
    if (t < out_n) out[t] = 0.0f;
}

// -------- per-node: p[n][k] = Wx'[k] . x[n]  (weights from constant/uniform path) --------
__global__ void __launch_bounds__(NT) node_kernel(const float* __restrict__ x, int n_nodes) {
    int n = blockIdx.x * blockDim.x + threadIdx.x;
    if (n >= n_nodes) return;
    float acc[HID];
#pragma unroll
    for (int k = 0; k < HID; k++) acc[k] = 0.0f;
    const float4* xr = (const float4*)(x + (size_t)n * D_NODE);
#pragma unroll
    for (int jj = 0; jj < D_NODE / 4; jj++) {
        float4 v = __ldg(xr + jj);
#pragma unroll
        for (int k = 0; k < HID; k++) {
            acc[k] += c_par.Wx[k][jj*4+0] * v.x + c_par.Wx[k][jj*4+1] * v.y
                    + c_par.Wx[k][jj*4+2] * v.z + c_par.Wx[k][jj*4+3] * v.w;
        }
    }
    float4* po = (float4*)(g_p + (size_t)n * HID);
    po[0] = make_float4(acc[0], acc[1], acc[2], acc[3]);
    po[1] = make_float4(acc[4], acc[5], acc[6], acc[7]);
    po[2] = make_float4(acc[8], acc[9], acc[10], acc[11]);
    po[3] = make_float4(acc[12], acc[13], acc[14], acc[15]);
}

// -------- per-edge: msg + pooled accumulation --------
__global__ void __launch_bounds__(THREADS) edge_kernel(
    const float* __restrict__ edge_attr,
    const int* __restrict__ ei,             // [2][E] int32
    const int* __restrict__ batch,          // [N]    int32
    float* __restrict__ out,                // [G]
    int n_edges) {
    extern __shared__ float sm[];
    float* sRow = sm;                                   // TILE * RSTRIDE floats
    float* bins = sm + TILE * RSTRIDE;                  // 128
    int*   sSrc = (int*)(bins + N_GRAPHS_C);            // TILE

    const int t  = threadIdx.x;
    const int e0 = blockIdx.x * TILE;
    const int e  = e0 + t;
    const bool v = e < n_edges;

    int src = 0, g = 0;
    if (v) {
        src = __ldg(ei + e);
        g   = __ldg(batch + __ldg(ei + n_edges + e));
    }
    sSrc[t] = src;
    if (t < N_GRAPHS_C) bins[t] = 0.0f;
    __syncthreads();

    // stage edge_attr per-edge rows (coalesced LDG.128, conflict-free STS.128)
    {
        const float4* ga = (const float4*)edge_attr;
        const long long base  = (long long)e0 * (D_EDGE / 4);
        const long long total = (long long)n_edges * (D_EDGE / 4);
#pragma unroll
        for (int r = 0; r < (TILE * (D_EDGE / 4)) / THREADS; r++) {   // 8 rounds
            int idx = r * THREADS + t;
            float4 w = make_float4(0.f, 0.f, 0.f, 0.f);
            if (base + idx < total) w = __ldg(ga + base + idx);
            int el = idx >> 3;
            int c  = idx & 7;
            *(float4*)(sRow + el * RSTRIDE + c * 4) = w;
        }
        // cooperative p gather: 4 lanes per edge -> 8 lines per LDG instr
#pragma unroll
        for (int r = 0; r < (TILE * 4) / THREADS; r++) {              // 4 rounds
            int idx = r * THREADS + t;
            int el  = idx >> 2;
            int q   = idx & 3;
            int s   = sSrc[el];
            float4 pv = __ldg((const float4*)g_p + (size_t)s * 4 + q);
            *(float4*)(sRow + el * RSTRIDE + D_EDGE + q * 4) = pv;
        }
    }
    __syncthreads();

    // acc = p + folded bias
    float acc[HID];
    {
        const float* myRow = sRow + t * RSTRIDE;
#pragma unroll
        for (int q = 0; q < 4; q++) {
            float4 pv = *(const float4*)(myRow + D_EDGE + q * 4);
            acc[q*4+0] = pv.x + c_par.B[q*4+0];
            acc[q*4+1] = pv.y + c_par.B[q*4+1];
            acc[q*4+2] = pv.z + c_par.B[q*4+2];
            acc[q*4+3] = pv.w + c_par.B[q*4+3];
        }
        // edge-part: 32 j, weights via constant (uniform datapath)
#pragma unroll
        for (int c = 0; c < 8; c++) {
            float4 a4 = *(const float4*)(myRow + c * 4);
            float av[4] = {a4.x, a4.y, a4.z, a4.w};
#pragma unroll
            for (int jj = 0; jj < 4; jj++) {
                float a = av[jj];
#pragma unroll
                for (int k = 0; k < HID; k++)
                    acc[k] += c_par.W[c*4+jj][k] * a;
            }
        }
    }

    if (v) {
        float m = c_par.b2;
#pragma unroll
        for (int k = 0; k < HID; k++) m += c_par.W2[k] * fmaxf(acc[k], 0.0f);
        atomicAdd(&bins[g], m);
    }
    __syncthreads();
    if (t < N_GRAPHS_C) atomicAdd(&out[t], bins[t]);
}

#define EDGE_SMEM ((TILE * RSTRIDE + N_GRAPHS_C) * 4 + TILE * 4)

extern "C" void kernel_launch(void* const* d_in, const int* in_sizes, int n_in,
                              void* d_out, int out_size) {
    const float* x         = (const float*)d_in[0];
    const float* edge_attr = (const float*)d_in[1];
    const int*   ei        = (const int*)d_in[2];
    const int*   batch     = (const int*)d_in[3];
    const float* W1        = (const float*)d_in[4];
    const float* b1        = (const float*)d_in[5];
    const float* gamma     = (const float*)d_in[6];
    const float* beta      = (const float*)d_in[7];
    const float* rm        = (const float*)d_in[8];
    const float* rv        = (const float*)d_in[9];
    const float* W2        = (const float*)d_in[10];
    const float* b2        = (const float*)d_in[11];
    float* out = (float*)d_out;

    const int n_nodes = in_sizes[0] / D_NODE;
    const int n_edges = in_sizes[1] / D_EDGE;

    cudaFuncSetAttribute(edge_kernel, cudaFuncAttributeMaxDynamicSharedMemorySize, EDGE_SMEM);

    void *c_addr = nullptr, *g_addr = nullptr;
    cudaGetSymbolAddress(&c_addr, c_par);
    cudaGetSymbolAddress(&g_addr, g_par);

    prep_kernel<<<8, 256>>>(W1, b1, gamma, beta, rm, rv, W2, b2, out, out_size);
    cudaMemcpyAsync(c_addr, g_addr, sizeof(CP), cudaMemcpyDeviceToDevice, 0);
    node_kernel<<<(n_nodes + NT - 1) / NT, NT>>>(x, n_nodes);
    edge_kernel<<<(n_edges + TILE - 1) / TILE, THREADS, EDGE_SMEM>>>(edge_attr, ei, batch, out, n_edges);
}